// round 16
// baseline (speedup 1.0000x reference)
#include <cuda_runtime.h>
#include <cuda_bf16.h>
#include <cstdint>

// QuantizedEmbedding: out[i, d] = code[quant_weight[x[i], d]] * absmax[x[i] >> 2]
//   x: int32[16384]  qw: int32[50304,1024]  absmax: f32[12576]  code: f32[256]
//   out: f32[16384,1024]   (block index == v>>2 since (v%4)*1024 + d < 4096)
//
// R16 (final): best-measured structure across 12 variants. 128 MB/replay of
// combined LTS traffic (64MB L2-resident gathered reads + 64MB writes) sits
// at the ~6300 B/cyc chip LTS cap at memory-bound DVFS clocks -> ~18.9us is
// the byte floor for this format. Structure: persistent CTAs (148x4),
// double-buffered group prefetch (TOK=4), 8-way bank-interleaved codebook,
// __ldcg gather reads, __stcs streaming stores (keeps gathered rows
// L2-resident across graph replays: proven worth 4.4us vs plain stores).

#define TOK 4

__global__ void __launch_bounds__(256, 4)
qembed_kernel(const int* __restrict__ x,
              const int4* __restrict__ qw,
              const float* __restrict__ absmax,
              const float* __restrict__ code,
              float4* __restrict__ out,
              int n_groups)
{
    __shared__ __align__(16) float s_code[256 * 8];
    const int t = threadIdx.x;
    const int c = t & 7;               // lane class -> private 4-bank set

    {
        // Vectorized fill: 2x STS.128 per thread instead of 8x STS.32.
        const float cv = code[t];
        const float4 v4 = make_float4(cv, cv, cv, cv);
        *(float4*)&s_code[t * 8 + 0] = v4;
        *(float4*)&s_code[t * 8 + 4] = v4;
    }
    __syncthreads();

    const int G = gridDim.x;
    int g = blockIdx.x;

    // Prefetch first group.
    int4  q[TOK];
    float sc[TOK];
    #pragma unroll
    for (int k = 0; k < TOK; k++) {
        const int v = x[g * TOK + k];
        q[k]  = __ldcg(&qw[(size_t)v * 256 + t]);
        sc[k] = __ldg(&absmax[v >> 2]);
    }

    while (true) {
        const int gn = g + G;

        int4  qn[TOK];
        float scn[TOK];
        if (gn < n_groups) {
            // Issue next group's independent loads before processing current.
            #pragma unroll
            for (int k = 0; k < TOK; k++) {
                const int v = x[gn * TOK + k];
                qn[k]  = __ldcg(&qw[(size_t)v * 256 + t]);
                scn[k] = __ldg(&absmax[v >> 2]);
            }
        }

        // Process current group (LDS lookups + streaming stores).
        #pragma unroll
        for (int k = 0; k < TOK; k++) {
            float4 o;
            o.x = s_code[q[k].x * 8 + c] * sc[k];
            o.y = s_code[q[k].y * 8 + c] * sc[k];
            o.z = s_code[q[k].z * 8 + c] * sc[k];
            o.w = s_code[q[k].w * 8 + c] * sc[k];
            __stcs(&out[(size_t)(g * TOK + k) * 256 + t], o);
        }

        if (gn >= n_groups) break;
        g = gn;
        #pragma unroll
        for (int k = 0; k < TOK; k++) { q[k] = qn[k]; sc[k] = scn[k]; }
    }
}

extern "C" void kernel_launch(void* const* d_in, const int* in_sizes, int n_in,
                              void* d_out, int out_size)
{
    // Bind inputs by element count (all four distinct) — robust to ordering.
    const int*   x      = nullptr;  int n_tokens = 0;
    const int4*  qw     = nullptr;
    const float* absmax = nullptr;
    const float* code   = nullptr;

    for (int i = 0; i < n_in; i++) {
        const int sz = in_sizes[i];
        if (sz == 256)            code   = (const float*)d_in[i];
        else if (sz == 12576)     absmax = (const float*)d_in[i];
        else if (sz > 1000000)    qw     = (const int4*)d_in[i];
        else                      { x = (const int*)d_in[i]; n_tokens = sz; }
    }

    float4* out = (float4*)d_out;
    const int n_groups = n_tokens / TOK;         // 4096
    const int grid = 148 * 4;                    // persistent: one wave at occ 4
    qembed_kernel<<<grid, 256>>>(x, qw, absmax, code, out, n_groups);
}

// round 17
// speedup vs baseline: 1.0033x; 1.0033x over previous
#include <cuda_runtime.h>
#include <cuda_bf16.h>
#include <cstdint>

// QuantizedEmbedding: out[i, d] = code[quant_weight[x[i], d]] * absmax[x[i] >> 2]
//   x: int32[16384]  qw: int32[50304,1024]  absmax: f32[12576]  code: f32[256]
//   out: f32[16384,1024]   (block index == v>>2 since (v%4)*1024 + d < 4096)
//
// FINAL (== R11, best measured 18.91us). At the chip SM<->LTS byte floor:
// 128 MB/replay obligatory traffic (64MB gathered reads, L2-resident in
// graph-replay steady state thanks to __stcs; 64MB fp32 writes) / ~6300 B/cyc
// LTS cap ~= 18.5-19us. Verified by 13 structural variants (occ 44-95%,
// MLP 1-8, LDS conflict 1-4x, L1/L2 policies, STG/STG.256/TMA stores,
// persistent & non-persistent) all converging to 18.8-19.2us with every
// per-unit SOL% < 60% — the shared byte pipe, not any one unit, binds.
//
// Structure: persistent CTAs (148x4), double-buffered group prefetch (TOK=4),
// 8-way bank-interleaved smem codebook, __ldcg gather reads, __stcs streaming
// stores (proven worth 4.4us: keeps gathered rows L2-resident across replays).

#define TOK 4

__global__ void __launch_bounds__(256, 4)
qembed_kernel(const int* __restrict__ x,
              const int4* __restrict__ qw,
              const float* __restrict__ absmax,
              const float* __restrict__ code,
              float4* __restrict__ out,
              int n_groups)
{
    __shared__ float s_code[256 * 8];
    const int t = threadIdx.x;
    const int c = t & 7;               // lane class -> private 4-bank set

    {
        const float cv = code[t];
        #pragma unroll
        for (int r = 0; r < 8; r++)
            s_code[t * 8 + r] = cv;
    }
    __syncthreads();

    const int G = gridDim.x;
    int g = blockIdx.x;

    // Prefetch first group.
    int4  q[TOK];
    float sc[TOK];
    #pragma unroll
    for (int k = 0; k < TOK; k++) {
        const int v = x[g * TOK + k];
        q[k]  = __ldcg(&qw[(size_t)v * 256 + t]);
        sc[k] = __ldg(&absmax[v >> 2]);
    }

    while (true) {
        const int gn = g + G;

        int4  qn[TOK];
        float scn[TOK];
        if (gn < n_groups) {
            // Issue next group's independent loads before processing current.
            #pragma unroll
            for (int k = 0; k < TOK; k++) {
                const int v = x[gn * TOK + k];
                qn[k]  = __ldcg(&qw[(size_t)v * 256 + t]);
                scn[k] = __ldg(&absmax[v >> 2]);
            }
        }

        // Process current group (LDS lookups + streaming stores).
        #pragma unroll
        for (int k = 0; k < TOK; k++) {
            float4 o;
            o.x = s_code[q[k].x * 8 + c] * sc[k];
            o.y = s_code[q[k].y * 8 + c] * sc[k];
            o.z = s_code[q[k].z * 8 + c] * sc[k];
            o.w = s_code[q[k].w * 8 + c] * sc[k];
            __stcs(&out[(size_t)(g * TOK + k) * 256 + t], o);
        }

        if (gn >= n_groups) break;
        g = gn;
        #pragma unroll
        for (int k = 0; k < TOK; k++) { q[k] = qn[k]; sc[k] = scn[k]; }
    }
}

extern "C" void kernel_launch(void* const* d_in, const int* in_sizes, int n_in,
                              void* d_out, int out_size)
{
    // Bind inputs by element count (all four distinct) — robust to ordering.
    const int*   x      = nullptr;  int n_tokens = 0;
    const int4*  qw     = nullptr;
    const float* absmax = nullptr;
    const float* code   = nullptr;

    for (int i = 0; i < n_in; i++) {
        const int sz = in_sizes[i];
        if (sz == 256)            code   = (const float*)d_in[i];
        else if (sz == 12576)     absmax = (const float*)d_in[i];
        else if (sz > 1000000)    qw     = (const int4*)d_in[i];
        else                      { x = (const int*)d_in[i]; n_tokens = sz; }
    }

    float4* out = (float4*)d_out;
    const int n_groups = n_tokens / TOK;         // 4096
    const int grid = 148 * 4;                    // persistent: one wave at occ 4
    qembed_kernel<<<grid, 256>>>(x, qw, absmax, code, out, n_groups);
}